// round 11
// baseline (speedup 1.0000x reference)
#include <cuda_runtime.h>
#include <cstdint>

// NLinear via mma.sync tf32 (base sm_100 target).
// R11 = R10 resubmitted verbatim (previous round was an infra failure, not a
// kernel result). A-side cvt.rna.tf32 removed — raw fp32 bits go straight
// from ldmatrix into mma (HW truncates to tf32). B keeps RN conversion so the
// systematic truncation bias stays ~2.4e-4 (one side only).
// out[b,n,o] = sum_i x[b,n,i]*W[n,i,o] + bias[n,o]

static constexpr int N_POS = 128;
static constexpr int D_IN  = 512;
static constexpr int D_OUT = 512;
static constexpr int BATCH = 256;
static constexpr int XSTR  = N_POS * D_IN;   // 65536: batch-row stride in x/out
static constexpr int WSTR  = D_IN * D_OUT;   // 262144

static constexpr int BM = 128;
static constexpr int BN = 128;
static constexpr int BK = 32;
static constexpr int KITERS = D_IN / BK;     // 16

static constexpr int ASTR = 36;              // A: ldmatrix rows stride 144B -> all 32 banks
static constexpr int BSTR = 136;             // B: bank = 8t+g (all 32 distinct)
static constexpr int A_ELEMS = BM * ASTR;    // 4608
static constexpr int B_ELEMS = BK * BSTR;    // 4352
static constexpr int STAGE   = A_ELEMS + B_ELEMS;  // 8960 floats
static constexpr int SMEM_BYTES = 2 * STAGE * 4;   // 71680

__device__ __forceinline__ void cp16(float* dst_smem, const float* src) {
    uint32_t d = (uint32_t)__cvta_generic_to_shared(dst_smem);
    asm volatile("cp.async.cg.shared.global [%0], [%1], 16;" :: "r"(d), "l"(src));
}
__device__ __forceinline__ void cp_commit() {
    asm volatile("cp.async.commit_group;" ::: "memory");
}
template <int N>
__device__ __forceinline__ void cp_wait() {
    asm volatile("cp.async.wait_group %0;" :: "n"(N) : "memory");
}
__device__ __forceinline__ uint32_t f2tf32(float f) {
    uint32_t r;
    asm("cvt.rna.tf32.f32 %0, %1;" : "=r"(r) : "f"(f));
    return r;
}
__device__ __forceinline__ void ldmatrix_x4(uint32_t& r0, uint32_t& r1,
                                            uint32_t& r2, uint32_t& r3,
                                            uint32_t smem_addr) {
    asm volatile("ldmatrix.sync.aligned.m8n8.x4.shared.b16 {%0,%1,%2,%3}, [%4];"
                 : "=r"(r0), "=r"(r1), "=r"(r2), "=r"(r3)
                 : "r"(smem_addr));
}
__device__ __forceinline__ void mma_tf32(float c[4],
                                         const uint32_t a[4],
                                         const uint32_t b[2]) {
    asm volatile(
        "mma.sync.aligned.m16n8k8.row.col.f32.tf32.tf32.f32 "
        "{%0,%1,%2,%3}, {%4,%5,%6,%7}, {%8,%9}, {%0,%1,%2,%3};"
        : "+f"(c[0]), "+f"(c[1]), "+f"(c[2]), "+f"(c[3])
        : "r"(a[0]), "r"(a[1]), "r"(a[2]), "r"(a[3]), "r"(b[0]), "r"(b[1]));
}

__device__ __forceinline__ void prefetch_stage(float* sm, int stage,
                                               const float* xb, const float* wb,
                                               int k0, int tid)
{
    float* As = sm + stage * STAGE;
    float* Bs = As + A_ELEMS;
    // A tile: 128 rows x 32 floats (128B/row) = 1024 x 16B chunks
    #pragma unroll
    for (int j = 0; j < 4; j++) {
        int c  = tid + j * 256;
        int m  = c >> 3;
        int kc = c & 7;
        cp16(As + m * ASTR + kc * 4, xb + (size_t)m * XSTR + k0 + kc * 4);
    }
    // B tile: 32 rows x 128 floats (512B/row) = 1024 x 16B chunks
    #pragma unroll
    for (int j = 0; j < 4; j++) {
        int c  = tid + j * 256;
        int kr = c >> 5;
        int nc = c & 31;
        cp16(Bs + kr * BSTR + nc * 4, wb + (size_t)(k0 + kr) * D_OUT + nc * 4);
    }
    cp_commit();
}

__global__ __launch_bounds__(256, 2)
void nlinear_mma_kernel(const float* __restrict__ x,
                        const float* __restrict__ w,
                        const float* __restrict__ bias,
                        float* __restrict__ out)
{
    extern __shared__ float sm[];

    const int tid = threadIdx.x;
    const int wid = tid >> 5;
    const int lid = tid & 31;
    const int g   = lid >> 2;   // group id (row within 8)
    const int t   = lid & 3;    // thread-in-group

    const int n     = blockIdx.z;
    const int obase = blockIdx.x * BN;
    const int mbase = blockIdx.y * BM;

    // warp grid 2 (M) x 4 (N): warp tile 64 x 32
    const int wm0 = (wid & 1) * 64;
    const int wn0 = (wid >> 1) * 32;

    const float* xb = x + (size_t)mbase * XSTR + (size_t)n * D_IN;
    const float* wb = w + (size_t)n * WSTR + obase;

    // ldmatrix per-lane byte offset within the A tile:
    // row = wm0 + (lid & 15), col add = (lid>>4)*4 tf32 columns
    const uint32_t smem_u32 = (uint32_t)__cvta_generic_to_shared(sm);
    const uint32_t a_lm_off =
        (uint32_t)(((wm0 + (lid & 15)) * ASTR + (lid >> 4) * 4) * 4);

    float acc[4][4][4];
    #pragma unroll
    for (int mt = 0; mt < 4; mt++)
        #pragma unroll
        for (int nt = 0; nt < 4; nt++)
            #pragma unroll
            for (int q = 0; q < 4; q++)
                acc[mt][nt][q] = 0.0f;

    prefetch_stage(sm, 0, xb, wb, 0, tid);

    for (int it = 0; it < KITERS; ++it) {
        if (it + 1 < KITERS) {
            prefetch_stage(sm, (it + 1) & 1, xb, wb, (it + 1) * BK, tid);
            cp_wait<1>();
        } else {
            cp_wait<0>();
        }
        __syncthreads();

        const uint32_t As_u32 = smem_u32 + (uint32_t)((it & 1) * STAGE * 4);
        const float*   Bs     = sm + (it & 1) * STAGE + A_ELEMS;

        #pragma unroll
        for (int ks = 0; ks < 4; ks++) {
            const int kk = ks * 8;
            uint32_t a[4][4];
            uint32_t b[4][2];
            #pragma unroll
            for (int mt = 0; mt < 4; mt++) {
                // Raw fp32 bits; tensor core truncates to tf32 (RZ on A only).
                ldmatrix_x4(a[mt][0], a[mt][1], a[mt][2], a[mt][3],
                            As_u32 + a_lm_off + (uint32_t)((mt * 16 * ASTR + kk) * 4));
            }
            #pragma unroll
            for (int nt = 0; nt < 4; nt++) {
                const float* bp = Bs + (kk + t) * BSTR + wn0 + 8 * nt + g;
                b[nt][0] = f2tf32(bp[0]);
                b[nt][1] = f2tf32(bp[4 * BSTR]);
            }
            #pragma unroll
            for (int mt = 0; mt < 4; mt++)
                #pragma unroll
                for (int nt = 0; nt < 4; nt++)
                    mma_tf32(acc[mt][nt], a[mt], b[nt]);
        }
        __syncthreads();
    }

    // ---- Epilogue: bias + store ----
    const float* brow = bias + (size_t)n * D_OUT + obase;
    #pragma unroll
    for (int mt = 0; mt < 4; mt++) {
        const int r0 = mbase + wm0 + 16 * mt + g;
        float* o0 = out + (size_t)r0 * XSTR + (size_t)n * D_OUT + obase;
        float* o1 = o0 + (size_t)8 * XSTR;
        #pragma unroll
        for (int nt = 0; nt < 4; nt++) {
            const int col = wn0 + 8 * nt + 2 * t;
            float2 bv = *(const float2*)(brow + col);
            float2 v0, v1;
            v0.x = acc[mt][nt][0] + bv.x;
            v0.y = acc[mt][nt][1] + bv.y;
            v1.x = acc[mt][nt][2] + bv.x;
            v1.y = acc[mt][nt][3] + bv.y;
            *(float2*)(o0 + col) = v0;
            *(float2*)(o1 + col) = v1;
        }
    }
}

extern "C" void kernel_launch(void* const* d_in, const int* in_sizes, int n_in,
                              void* d_out, int out_size)
{
    const float* x    = (const float*)d_in[0];
    const float* w    = (const float*)d_in[1];
    const float* bias = (const float*)d_in[2];
    float* out        = (float*)d_out;

    cudaFuncSetAttribute(nlinear_mma_kernel,
                         cudaFuncAttributeMaxDynamicSharedMemorySize, SMEM_BYTES);

    dim3 grid(D_OUT / BN, BATCH / BM, N_POS);   // (4, 2, 128)
    dim3 block(256);
    nlinear_mma_kernel<<<grid, block, SMEM_BYTES>>>(x, w, bias, out);
}